// round 9
// baseline (speedup 1.0000x reference)
#include <cuda_runtime.h>
#include <cstdint>

// Capsule layer, two-kernel split (R8):
//   prep:  permute W into tf32 mma fragment layout (once)
//   conv:  tf32 mma.sync GEMM votes[i][128px,128cf].
//          R8: 512-thread blocks, warp tile M32xN32 (acc 32 regs) ->
//          regs<=64 -> 2x512 threads/SM = 50% occupancy (was 25%).
//          W fragments LDG'd straight from L2-resident image (no W smem).
//   routing: fp32 dynamic routing, one warp per pixel
//
//   x [32,32,32,8,16] f32   W [8,3,3,16,128] f32   b [1,1,8,16] f32
//   out [32,32,32,8,16] f32

#define EPS_SQ 1e-7f
#define XT_PITCH 232        // 232 % 32 == 8 -> conflict-free A-frag LDS

__device__ float    g_votes[32768 * 1024];           // [px][i*128+cf]
__device__ uint32_t g_Wfrag[8 * 18 * 16 * 64];

__device__ __forceinline__ uint32_t tf32_rna(float f) {
    uint32_t u;
    asm("cvt.rna.tf32.f32 %0, %1;" : "=r"(u) : "f"(f));
    return u;
}
__device__ __forceinline__ void mma8(float c[4], const uint4& a, const uint2& b) {
    asm volatile(
        "mma.sync.aligned.m16n8k8.row.col.f32.tf32.tf32.f32 "
        "{%0,%1,%2,%3}, {%4,%5,%6,%7}, {%8,%9}, {%0,%1,%2,%3};"
        : "+f"(c[0]), "+f"(c[1]), "+f"(c[2]), "+f"(c[3])
        : "r"(a.x), "r"(a.y), "r"(a.z), "r"(a.w), "r"(b.x), "r"(b.y));
}

// Pre-permuted tf32 weight fragments: [i][kk(18)][nt(16)][lane] uint2,
// (b0,b1) = W[k=8kk+c4][cf=8nt+g], W[k+4][cf].  (g=lane>>2, c4=lane&3)
__global__ void prep_weights(const float* __restrict__ W) {
    int gi = blockIdx.x * 256 + threadIdx.x;      // 0..73727
    int lane = gi & 31;
    int nt   = (gi >> 5) & 15;
    int r    = gi >> 9;                           // i*18 + kk
    int kk = r % 18, i = r / 18;
    int g = lane >> 2, c4 = lane & 3;
    int cf = nt * 8 + g;
    int k0 = kk * 8 + c4, k1 = k0 + 4;
    float w0 = W[((i * 9 + (k0 >> 4)) * 16 + (k0 & 15)) * 128 + cf];
    float w1 = W[((i * 9 + (k1 >> 4)) * 16 + (k1 & 15)) * 128 + cf];
    uint2 o;
    o.x = tf32_rna(w0);
    o.y = tf32_rna(w1);
    reinterpret_cast<uint2*>(g_Wfrag)[gi] = o;
}

// ---- K1: conv votes GEMM. grid (256 m-blocks, 8 i), 512 threads ----
// Block = 128 px (4 h-rows x 32 w of batch mblk>>3), 128 cf, one capsule i.
// 16 warps: wm = wid&3 (M32 = h-row), wn = wid>>2 (N32 = 4 n8 tiles).
__global__ __launch_bounds__(512, 2)
void conv_votes_kernel(const float* __restrict__ x)
{
    __shared__ uint32_t x_t[16 * XT_PITCH];          // tf32 bits, [fin][6*34 pix]

    const int t = threadIdx.x, lane = t & 31, wid = t >> 5;
    const int mblk = blockIdx.x, i = blockIdx.y;
    const int b = mblk >> 3, h0 = (mblk & 7) << 2;

    // load x tile transposed + tf32-convert, zero-pad SAME borders
    for (int e4 = t; e4 < 816; e4 += 512) {
        int pix = e4 >> 2, q = e4 & 3;
        int r = pix / 34, c = pix - r * 34;
        int hh = h0 + r - 1, ww = c - 1;
        float4 v = make_float4(0.f, 0.f, 0.f, 0.f);
        if (hh >= 0 && hh < 32 && ww >= 0 && ww < 32)
            v = reinterpret_cast<const float4*>(x)
                  [((b * 32 + hh) * 32 + ww) * 32 + i * 4 + q];
        x_t[(q * 4 + 0) * XT_PITCH + pix] = tf32_rna(v.x);
        x_t[(q * 4 + 1) * XT_PITCH + pix] = tf32_rna(v.y);
        x_t[(q * 4 + 2) * XT_PITCH + pix] = tf32_rna(v.z);
        x_t[(q * 4 + 3) * XT_PITCH + pix] = tf32_rna(v.w);
    }
    __syncthreads();

    const int g = lane >> 2, c4 = lane & 3;
    const int wm = wid & 3, wn = wid >> 2;

    float acc[2][4][4];
    #pragma unroll
    for (int mt = 0; mt < 2; mt++)
        #pragma unroll
        for (int n = 0; n < 4; n++)
            #pragma unroll
            for (int j = 0; j < 4; j++) acc[mt][n][j] = 0.f;

    // B fragments straight from L2-resident image
    const uint2* wf = reinterpret_cast<const uint2*>(g_Wfrag) +
                      (size_t)(i * 288 + wn * 4) * 32 + lane;

    #pragma unroll 6
    for (int kk = 0; kk < 18; kk++) {
        const int kyx = kk >> 1;
        const int ky = kyx / 3, kx = kyx - ky * 3;
        const int fin0 = ((kk & 1) << 3) + c4;
        uint2 bb[4];
        #pragma unroll
        for (int n = 0; n < 4; n++)
            bb[n] = __ldg(&wf[(size_t)(kk * 16 + n) * 32]);
        uint4 a[2];
        #pragma unroll
        for (int mt = 0; mt < 2; mt++) {
            const uint32_t* xp = x_t + fin0 * XT_PITCH +
                                 (wm + ky) * 34 + mt * 16 + g + kx;
            a[mt].x = xp[0];
            a[mt].y = xp[8];
            a[mt].z = xp[4 * XT_PITCH];
            a[mt].w = xp[4 * XT_PITCH + 8];
        }
        #pragma unroll
        for (int n = 0; n < 4; n++) {
            mma8(acc[0][n], a[0], bb[n]);
            mma8(acc[1][n], a[1], bb[n]);
        }
    }

    // store votes: [px][i*128 + cf]
    float* vp = g_votes + (size_t)(mblk * 128) * 1024 +
                i * 128 + wn * 32 + 2 * c4;
    #pragma unroll
    for (int mt = 0; mt < 2; mt++) {
        const int m0 = wm * 32 + mt * 16 + g;
        #pragma unroll
        for (int n = 0; n < 4; n++) {
            float* p0 = vp + (size_t)m0 * 1024 + n * 8;
            *reinterpret_cast<float2*>(p0) =
                make_float2(acc[mt][n][0], acc[mt][n][1]);
            *reinterpret_cast<float2*>(p0 + 8 * 1024) =
                make_float2(acc[mt][n][2], acc[mt][n][3]);
        }
    }
}

// ---- K2: routing. grid 4096, 256 threads; warp w routes px = blk*8+w ----
__global__ __launch_bounds__(256)
void routing_kernel(const float* __restrict__ bias, float* __restrict__ out)
{
    const int t = threadIdx.x, lane = t & 31, wid = t >> 5;
    const int px = blockIdx.x * 8 + wid;

    const float4 bv = reinterpret_cast<const float4*>(bias)[lane];
    const float4* vg = reinterpret_cast<const float4*>(g_votes) + (size_t)px * 256;

    float4 v[8];
    #pragma unroll
    for (int i = 0; i < 8; i++)
        v[i] = vg[i * 32 + lane];

    float logit[8];
    #pragma unroll
    for (int i = 0; i < 8; i++) logit[i] = 0.f;
    float4 act = make_float4(0.f, 0.f, 0.f, 0.f);

    #pragma unroll
    for (int r = 0; r < 3; r++) {
        float route[8];
        if (r == 0) {
            #pragma unroll
            for (int i = 0; i < 8; i++) route[i] = 0.125f;   // softmax(0)
        } else {
            #pragma unroll
            for (int i = 0; i < 8; i++) {
                float m = logit[i];
                m = fmaxf(m, __shfl_xor_sync(0xffffffffu, m, 4));
                m = fmaxf(m, __shfl_xor_sync(0xffffffffu, m, 8));
                m = fmaxf(m, __shfl_xor_sync(0xffffffffu, m, 16));
                float e = __expf(logit[i] - m);
                float s = e;
                s += __shfl_xor_sync(0xffffffffu, s, 4);
                s += __shfl_xor_sync(0xffffffffu, s, 8);
                s += __shfl_xor_sync(0xffffffffu, s, 16);
                route[i] = e / s;
            }
        }
        float4 pre = bv;
        #pragma unroll
        for (int i = 0; i < 8; i++) {
            pre.x += route[i] * v[i].x;
            pre.y += route[i] * v[i].y;
            pre.z += route[i] * v[i].z;
            pre.w += route[i] * v[i].w;
        }
        float s2 = pre.x * pre.x + pre.y * pre.y + pre.z * pre.z + pre.w * pre.w;
        s2 += __shfl_xor_sync(0xffffffffu, s2, 1);
        s2 += __shfl_xor_sync(0xffffffffu, s2, 2);
        float scale = s2 / (1.f + s2) * rsqrtf(s2 + EPS_SQ);
        act.x = scale * pre.x;
        act.y = scale * pre.y;
        act.z = scale * pre.z;
        act.w = scale * pre.w;
        if (r < 2) {
            #pragma unroll
            for (int i = 0; i < 8; i++) {
                float d = v[i].x * act.x + v[i].y * act.y +
                          v[i].z * act.z + v[i].w * act.w;
                d += __shfl_xor_sync(0xffffffffu, d, 1);
                d += __shfl_xor_sync(0xffffffffu, d, 2);
                logit[i] += d;
            }
        }
    }

    reinterpret_cast<float4*>(out)[(size_t)px * 32 + lane] = act;
}

extern "C" void kernel_launch(void* const* d_in, const int* in_sizes, int n_in,
                              void* d_out, int out_size)
{
    const float* x    = (const float*)d_in[0];
    const float* Wt   = (const float*)d_in[1];
    const float* bias = (const float*)d_in[2];
    float* out = (float*)d_out;
    (void)in_sizes; (void)n_in; (void)out_size;

    prep_weights<<<288, 256>>>(Wt);
    dim3 gridA(256, 8);
    conv_votes_kernel<<<gridA, 512>>>(x);
    routing_kernel<<<4096, 256>>>(bias, out);
}

// round 10
// speedup vs baseline: 1.3090x; 1.3090x over previous
#include <cuda_runtime.h>
#include <cuda_fp16.h>
#include <cstdint>

// Capsule layer, two-kernel split (R9):
//   prep:  permute W into fp16 m16n8k16 mma fragment layout (once)
//   conv:  fp16 mma.sync m16n8k16 GEMM votes[i][128px,128cf]; fp32 acc.
//          2x K per instruction vs tf32 m16n8k8 (same 11-bit mantissa!).
//   routing: fp32 dynamic routing, one warp per pixel
//
//   x [32,32,32,8,16] f32   W [8,3,3,16,128] f32   b [1,1,8,16] f32
//   out [32,32,32,8,16] f32

#define EPS_SQ 1e-7f
#define XH_PITCH 232        // half2 units; 232 % 32 == 8 -> conflict-free LDS

__device__ float    g_votes[32768 * 1024];          // [px][i*128+cf]
__device__ uint2    g_Wfrag[8 * 9 * 16 * 32];       // fp16 B fragments

__device__ __forceinline__ void mma16(float c[4], const uint4& a, const uint2& b) {
    asm volatile(
        "mma.sync.aligned.m16n8k16.row.col.f32.f16.f16.f32 "
        "{%0,%1,%2,%3}, {%4,%5,%6,%7}, {%8,%9}, {%0,%1,%2,%3};"
        : "+f"(c[0]), "+f"(c[1]), "+f"(c[2]), "+f"(c[3])
        : "r"(a.x), "r"(a.y), "r"(a.z), "r"(a.w), "r"(b.x), "r"(b.y));
}
__device__ __forceinline__ uint32_t h2u(__half2 h) {
    return *reinterpret_cast<uint32_t*>(&h);
}

// B fragments: [i][kk(9)][nt(16)][lane] uint2.
// lane: g = lane>>2 (cf within n8), c4 = lane&3 (k pair).
// b.x = half2(W[k=16kk+2c4][cf], W[16kk+2c4+1][cf]), b.y = same k+8.
// k maps to (kyx = kk, fin = k&15); W idx = ((i*9+kyx)*16+fin)*128+cf.
__global__ void prep_weights(const float* __restrict__ W) {
    int gi = blockIdx.x * 256 + threadIdx.x;      // 0..36863
    int lane = gi & 31;
    int nt   = (gi >> 5) & 15;
    int r    = gi >> 9;                           // i*9 + kk
    int kk = r % 9, i = r / 9;
    int g = lane >> 2, c4 = lane & 3;
    int cf = nt * 8 + g;
    const float* Wb = W + ((size_t)(i * 9 + kk) * 16) * 128 + cf;
    uint2 o;
    o.x = h2u(__floats2half2_rn(Wb[(2 * c4) * 128],     Wb[(2 * c4 + 1) * 128]));
    o.y = h2u(__floats2half2_rn(Wb[(2 * c4 + 8) * 128], Wb[(2 * c4 + 9) * 128]));
    g_Wfrag[gi] = o;
}

// ---- K1: conv votes GEMM. grid (256 m-blocks, 8 i), 256 threads ----
// Block = 128 px (4 h-rows x 32 w of batch mblk>>3), 128 cf, one capsule i.
// 8 warps: wm = wid>>1 (h-row, M32), wn = wid&1 (N64 = 8 n8 tiles).
// K = 144 = 9 k16 steps; step kk == tap (ky,kx) = (kk/3, kk%3), 16 fins.
__global__ __launch_bounds__(256, 2)
void conv_votes_kernel(const float* __restrict__ x)
{
    __shared__ uint32_t x_h[8 * XH_PITCH];   // half2 bits: [finp 8][pix 204]
    __shared__ uint2    s_w[9 * 16 * 32];    // W frags for this i (36 KB)

    const int t = threadIdx.x, lane = t & 31, wid = t >> 5;
    const int mblk = blockIdx.x, i = blockIdx.y;
    const int b = mblk >> 3, h0 = (mblk & 7) << 2;

    // stage W fragments: 2304 uint4, 9 per thread
    {
        const uint4* gw4 = reinterpret_cast<const uint4*>(g_Wfrag) + i * 2304;
        uint4* sw4 = reinterpret_cast<uint4*>(s_w);
        #pragma unroll
        for (int j = 0; j < 9; j++)
            sw4[j * 256 + t] = gw4[j * 256 + t];
    }

    // x tile (6 rows x 34 cols x 16 fin) -> packed half2, zero-pad SAME
    for (int e4 = t; e4 < 816; e4 += 256) {
        int pix = e4 >> 2, q = e4 & 3;       // q covers fin 4q..4q+3
        int r = pix / 34, c = pix - r * 34;
        int hh = h0 + r - 1, ww = c - 1;
        float4 v = make_float4(0.f, 0.f, 0.f, 0.f);
        if (hh >= 0 && hh < 32 && ww >= 0 && ww < 32)
            v = reinterpret_cast<const float4*>(x)
                  [((b * 32 + hh) * 32 + ww) * 32 + i * 4 + q];
        x_h[(q * 2 + 0) * XH_PITCH + pix] = h2u(__floats2half2_rn(v.x, v.y));
        x_h[(q * 2 + 1) * XH_PITCH + pix] = h2u(__floats2half2_rn(v.z, v.w));
    }
    __syncthreads();

    const int g = lane >> 2, c4 = lane & 3;
    const int wm = wid >> 1, wn = wid & 1;

    float acc[2][8][4];
    #pragma unroll
    for (int mt = 0; mt < 2; mt++)
        #pragma unroll
        for (int n = 0; n < 8; n++)
            #pragma unroll
            for (int j = 0; j < 4; j++) acc[mt][n][j] = 0.f;

    #pragma unroll
    for (int kk = 0; kk < 9; kk++) {
        const int ky = kk / 3, kx = kk - ky * 3;
        const int pbase = (wm + ky) * 34 + kx + g;
        uint4 a[2];
        #pragma unroll
        for (int mt = 0; mt < 2; mt++) {
            const int p0 = pbase + mt * 16;
            a[mt].x = x_h[c4 * XH_PITCH + p0];            // fin 2c4..,  px g
            a[mt].y = x_h[c4 * XH_PITCH + p0 + 8];        //             px g+8
            a[mt].z = x_h[(c4 + 4) * XH_PITCH + p0];      // fin 8+2c4.. px g
            a[mt].w = x_h[(c4 + 4) * XH_PITCH + p0 + 8];  //             px g+8
        }
        #pragma unroll
        for (int n = 0; n < 8; n++) {
            uint2 bb = s_w[(kk * 16 + wn * 8 + n) * 32 + lane];
            mma16(acc[0][n], a[0], bb);
            mma16(acc[1][n], a[1], bb);
        }
    }

    // store votes: [px][i*128 + cf]
    float* vp = g_votes + (size_t)(mblk * 128) * 1024 +
                i * 128 + wn * 64 + 2 * c4;
    #pragma unroll
    for (int mt = 0; mt < 2; mt++) {
        const int m0 = wm * 32 + mt * 16 + g;
        #pragma unroll
        for (int n = 0; n < 8; n++) {
            float* p0 = vp + (size_t)m0 * 1024 + n * 8;
            *reinterpret_cast<float2*>(p0) =
                make_float2(acc[mt][n][0], acc[mt][n][1]);
            *reinterpret_cast<float2*>(p0 + 8 * 1024) =
                make_float2(acc[mt][n][2], acc[mt][n][3]);
        }
    }
}

// ---- K2: routing. grid 4096, 256 threads; warp w routes px = blk*8+w ----
__global__ __launch_bounds__(256)
void routing_kernel(const float* __restrict__ bias, float* __restrict__ out)
{
    const int t = threadIdx.x, lane = t & 31, wid = t >> 5;
    const int px = blockIdx.x * 8 + wid;

    const float4 bv = reinterpret_cast<const float4*>(bias)[lane];
    const float4* vg = reinterpret_cast<const float4*>(g_votes) + (size_t)px * 256;

    float4 v[8];
    #pragma unroll
    for (int i = 0; i < 8; i++)
        v[i] = vg[i * 32 + lane];

    float logit[8];
    #pragma unroll
    for (int i = 0; i < 8; i++) logit[i] = 0.f;
    float4 act = make_float4(0.f, 0.f, 0.f, 0.f);

    #pragma unroll
    for (int r = 0; r < 3; r++) {
        float route[8];
        if (r == 0) {
            #pragma unroll
            for (int i = 0; i < 8; i++) route[i] = 0.125f;   // softmax(0)
        } else {
            #pragma unroll
            for (int i = 0; i < 8; i++) {
                float m = logit[i];
                m = fmaxf(m, __shfl_xor_sync(0xffffffffu, m, 4));
                m = fmaxf(m, __shfl_xor_sync(0xffffffffu, m, 8));
                m = fmaxf(m, __shfl_xor_sync(0xffffffffu, m, 16));
                float e = __expf(logit[i] - m);
                float s = e;
                s += __shfl_xor_sync(0xffffffffu, s, 4);
                s += __shfl_xor_sync(0xffffffffu, s, 8);
                s += __shfl_xor_sync(0xffffffffu, s, 16);
                route[i] = e / s;
            }
        }
        float4 pre = bv;
        #pragma unroll
        for (int i = 0; i < 8; i++) {
            pre.x += route[i] * v[i].x;
            pre.y += route[i] * v[i].y;
            pre.z += route[i] * v[i].z;
            pre.w += route[i] * v[i].w;
        }
        float s2 = pre.x * pre.x + pre.y * pre.y + pre.z * pre.z + pre.w * pre.w;
        s2 += __shfl_xor_sync(0xffffffffu, s2, 1);
        s2 += __shfl_xor_sync(0xffffffffu, s2, 2);
        float scale = s2 / (1.f + s2) * rsqrtf(s2 + EPS_SQ);
        act.x = scale * pre.x;
        act.y = scale * pre.y;
        act.z = scale * pre.z;
        act.w = scale * pre.w;
        if (r < 2) {
            #pragma unroll
            for (int i = 0; i < 8; i++) {
                float d = v[i].x * act.x + v[i].y * act.y +
                          v[i].z * act.z + v[i].w * act.w;
                d += __shfl_xor_sync(0xffffffffu, d, 1);
                d += __shfl_xor_sync(0xffffffffu, d, 2);
                logit[i] += d;
            }
        }
    }

    reinterpret_cast<float4*>(out)[(size_t)px * 32 + lane] = act;
}

extern "C" void kernel_launch(void* const* d_in, const int* in_sizes, int n_in,
                              void* d_out, int out_size)
{
    const float* x    = (const float*)d_in[0];
    const float* Wt   = (const float*)d_in[1];
    const float* bias = (const float*)d_in[2];
    float* out = (float*)d_out;
    (void)in_sizes; (void)n_in; (void)out_size;

    prep_weights<<<144, 256>>>(Wt);
    dim3 gridA(256, 8);
    conv_votes_kernel<<<gridA, 256>>>(x);
    routing_kernel<<<4096, 256>>>(bias, out);
}

// round 11
// speedup vs baseline: 1.4262x; 1.0895x over previous
#include <cuda_runtime.h>
#include <cuda_fp16.h>
#include <cstdint>

// Capsule layer, two-kernel split (R10):
//   prep:  permute W into fp16 m16n8k16 mma fragment layout (once)
//   conv:  fp16 mma.sync m16n8k16 GEMM votes[i][128px,128cf]; fp32 acc,
//          votes stored as fp16 (halves routing DRAM traffic).
//   routing: fp32 dynamic routing, one warp per pixel
//
//   x [32,32,32,8,16] f32   W [8,3,3,16,128] f32   b [1,1,8,16] f32
//   out [32,32,32,8,16] f32

#define EPS_SQ 1e-7f
#define XH_PITCH 232        // half2 units; 232 % 32 == 8 -> conflict-free LDS

__device__ __half   g_votes[32768 * 1024];          // [px][i*128+cf] fp16
__device__ uint2    g_Wfrag[8 * 9 * 16 * 32];       // fp16 B fragments

__device__ __forceinline__ void mma16(float c[4], const uint4& a, const uint2& b) {
    asm volatile(
        "mma.sync.aligned.m16n8k16.row.col.f32.f16.f16.f32 "
        "{%0,%1,%2,%3}, {%4,%5,%6,%7}, {%8,%9}, {%0,%1,%2,%3};"
        : "+f"(c[0]), "+f"(c[1]), "+f"(c[2]), "+f"(c[3])
        : "r"(a.x), "r"(a.y), "r"(a.z), "r"(a.w), "r"(b.x), "r"(b.y));
}
__device__ __forceinline__ uint32_t h2u(__half2 h) {
    return *reinterpret_cast<uint32_t*>(&h);
}

// B fragments: [i][kk(9)][nt(16)][lane] uint2.
// lane: g = lane>>2 (cf within n8), c4 = lane&3 (k pair).
// b.x = half2(W[k=16kk+2c4][cf], W[16kk+2c4+1][cf]), b.y = same k+8.
__global__ void prep_weights(const float* __restrict__ W) {
    int gi = blockIdx.x * 256 + threadIdx.x;      // 0..36863
    int lane = gi & 31;
    int nt   = (gi >> 5) & 15;
    int r    = gi >> 9;                           // i*9 + kk
    int kk = r % 9, i = r / 9;
    int g = lane >> 2, c4 = lane & 3;
    int cf = nt * 8 + g;
    const float* Wb = W + ((size_t)(i * 9 + kk) * 16) * 128 + cf;
    uint2 o;
    o.x = h2u(__floats2half2_rn(Wb[(2 * c4) * 128],     Wb[(2 * c4 + 1) * 128]));
    o.y = h2u(__floats2half2_rn(Wb[(2 * c4 + 8) * 128], Wb[(2 * c4 + 9) * 128]));
    g_Wfrag[gi] = o;
}

// ---- K1: conv votes GEMM. grid (256 m-blocks, 8 i), 256 threads ----
// Block = 128 px (4 h-rows x 32 w of batch mblk>>3), 128 cf, one capsule i.
// 8 warps: wm = wid>>1 (h-row, M32), wn = wid&1 (N64 = 8 n8 tiles).
// K = 144 = 9 k16 steps; step kk == tap (ky,kx) = (kk/3, kk%3), 16 fins.
__global__ __launch_bounds__(256, 2)
void conv_votes_kernel(const float* __restrict__ x)
{
    __shared__ uint32_t x_h[8 * XH_PITCH];   // half2 bits: [finp 8][pix 204]
    __shared__ uint2    s_w[9 * 16 * 32];    // W frags for this i (36 KB)

    const int t = threadIdx.x, lane = t & 31, wid = t >> 5;
    const int mblk = blockIdx.x, i = blockIdx.y;
    const int b = mblk >> 3, h0 = (mblk & 7) << 2;

    // stage W fragments: 2304 uint4, 9 per thread
    {
        const uint4* gw4 = reinterpret_cast<const uint4*>(g_Wfrag) + i * 2304;
        uint4* sw4 = reinterpret_cast<uint4*>(s_w);
        #pragma unroll
        for (int j = 0; j < 9; j++)
            sw4[j * 256 + t] = gw4[j * 256 + t];
    }

    // x tile (6 rows x 34 cols x 16 fin) -> packed half2, zero-pad SAME
    for (int e4 = t; e4 < 816; e4 += 256) {
        int pix = e4 >> 2, q = e4 & 3;       // q covers fin 4q..4q+3
        int r = pix / 34, c = pix - r * 34;
        int hh = h0 + r - 1, ww = c - 1;
        float4 v = make_float4(0.f, 0.f, 0.f, 0.f);
        if (hh >= 0 && hh < 32 && ww >= 0 && ww < 32)
            v = reinterpret_cast<const float4*>(x)
                  [((b * 32 + hh) * 32 + ww) * 32 + i * 4 + q];
        x_h[(q * 2 + 0) * XH_PITCH + pix] = h2u(__floats2half2_rn(v.x, v.y));
        x_h[(q * 2 + 1) * XH_PITCH + pix] = h2u(__floats2half2_rn(v.z, v.w));
    }
    __syncthreads();

    const int g = lane >> 2, c4 = lane & 3;
    const int wm = wid >> 1, wn = wid & 1;

    float acc[2][8][4];
    #pragma unroll
    for (int mt = 0; mt < 2; mt++)
        #pragma unroll
        for (int n = 0; n < 8; n++)
            #pragma unroll
            for (int j = 0; j < 4; j++) acc[mt][n][j] = 0.f;

    #pragma unroll
    for (int kk = 0; kk < 9; kk++) {
        const int ky = kk / 3, kx = kk - ky * 3;
        const int pbase = (wm + ky) * 34 + kx + g;
        uint4 a[2];
        #pragma unroll
        for (int mt = 0; mt < 2; mt++) {
            const int p0 = pbase + mt * 16;
            a[mt].x = x_h[c4 * XH_PITCH + p0];
            a[mt].y = x_h[c4 * XH_PITCH + p0 + 8];
            a[mt].z = x_h[(c4 + 4) * XH_PITCH + p0];
            a[mt].w = x_h[(c4 + 4) * XH_PITCH + p0 + 8];
        }
        #pragma unroll
        for (int n = 0; n < 8; n++) {
            uint2 bb = s_w[(kk * 16 + wn * 8 + n) * 32 + lane];
            mma16(acc[0][n], a[0], bb);
            mma16(acc[1][n], a[1], bb);
        }
    }

    // store votes as fp16: half idx = px*1024 + i*128 + wn*64 + n*8 + 2*c4
    uint32_t* vp = reinterpret_cast<uint32_t*>(g_votes) +
                   (size_t)(mblk * 128) * 512 + i * 64 + wn * 32 + c4;
    #pragma unroll
    for (int mt = 0; mt < 2; mt++) {
        const int m0 = wm * 32 + mt * 16 + g;
        #pragma unroll
        for (int n = 0; n < 8; n++) {
            vp[(size_t)m0 * 512 + n * 4] =
                h2u(__floats2half2_rn(acc[mt][n][0], acc[mt][n][1]));
            vp[(size_t)(m0 + 8) * 512 + n * 4] =
                h2u(__floats2half2_rn(acc[mt][n][2], acc[mt][n][3]));
        }
    }
}

// ---- K2: routing. grid 4096, 256 threads; warp w routes px = blk*8+w ----
__global__ __launch_bounds__(256)
void routing_kernel(const float* __restrict__ bias, float* __restrict__ out)
{
    const int t = threadIdx.x, lane = t & 31, wid = t >> 5;
    const int px = blockIdx.x * 8 + wid;

    const float4 bv = reinterpret_cast<const float4*>(bias)[lane];
    // uint2 = 4 halves; idx = (px*1024 + i*128 + lane*4)/4 = px*256 + i*32 + lane
    const uint2* vg = reinterpret_cast<const uint2*>(g_votes) + (size_t)px * 256;

    float4 v[8];
    #pragma unroll
    for (int i = 0; i < 8; i++) {
        uint2 raw = vg[i * 32 + lane];
        float2 f01 = __half22float2(*reinterpret_cast<__half2*>(&raw.x));
        float2 f23 = __half22float2(*reinterpret_cast<__half2*>(&raw.y));
        v[i] = make_float4(f01.x, f01.y, f23.x, f23.y);
    }

    float logit[8];
    #pragma unroll
    for (int i = 0; i < 8; i++) logit[i] = 0.f;
    float4 act = make_float4(0.f, 0.f, 0.f, 0.f);

    #pragma unroll
    for (int r = 0; r < 3; r++) {
        float route[8];
        if (r == 0) {
            #pragma unroll
            for (int i = 0; i < 8; i++) route[i] = 0.125f;   // softmax(0)
        } else {
            #pragma unroll
            for (int i = 0; i < 8; i++) {
                float m = logit[i];
                m = fmaxf(m, __shfl_xor_sync(0xffffffffu, m, 4));
                m = fmaxf(m, __shfl_xor_sync(0xffffffffu, m, 8));
                m = fmaxf(m, __shfl_xor_sync(0xffffffffu, m, 16));
                float e = __expf(logit[i] - m);
                float s = e;
                s += __shfl_xor_sync(0xffffffffu, s, 4);
                s += __shfl_xor_sync(0xffffffffu, s, 8);
                s += __shfl_xor_sync(0xffffffffu, s, 16);
                route[i] = e / s;
            }
        }
        float4 pre = bv;
        #pragma unroll
        for (int i = 0; i < 8; i++) {
            pre.x += route[i] * v[i].x;
            pre.y += route[i] * v[i].y;
            pre.z += route[i] * v[i].z;
            pre.w += route[i] * v[i].w;
        }
        float s2 = pre.x * pre.x + pre.y * pre.y + pre.z * pre.z + pre.w * pre.w;
        s2 += __shfl_xor_sync(0xffffffffu, s2, 1);
        s2 += __shfl_xor_sync(0xffffffffu, s2, 2);
        float scale = s2 / (1.f + s2) * rsqrtf(s2 + EPS_SQ);
        act.x = scale * pre.x;
        act.y = scale * pre.y;
        act.z = scale * pre.z;
        act.w = scale * pre.w;
        if (r < 2) {
            #pragma unroll
            for (int i = 0; i < 8; i++) {
                float d = v[i].x * act.x + v[i].y * act.y +
                          v[i].z * act.z + v[i].w * act.w;
                d += __shfl_xor_sync(0xffffffffu, d, 1);
                d += __shfl_xor_sync(0xffffffffu, d, 2);
                logit[i] += d;
            }
        }
    }

    reinterpret_cast<float4*>(out)[(size_t)px * 32 + lane] = act;
}

extern "C" void kernel_launch(void* const* d_in, const int* in_sizes, int n_in,
                              void* d_out, int out_size)
{
    const float* x    = (const float*)d_in[0];
    const float* Wt   = (const float*)d_in[1];
    const float* bias = (const float*)d_in[2];
    float* out = (float*)d_out;
    (void)in_sizes; (void)n_in; (void)out_size;

    prep_weights<<<144, 256>>>(Wt);
    dim3 gridA(256, 8);
    conv_votes_kernel<<<gridA, 256>>>(x);
    routing_kernel<<<4096, 256>>>(bias, out);
}

// round 12
// speedup vs baseline: 1.4492x; 1.0162x over previous
#include <cuda_runtime.h>
#include <cuda_fp16.h>
#include <cstdint>

// Capsule layer, two-kernel split (R11):
//   prep:  permute W into fp16 m16n8k16 fragment layout (coalesced via smem)
//   conv:  fp16 mma.sync m16n8k16 GEMM votes[i][128px,128cf]; fp32 acc,
//          fp16 vote store. R11: 512 threads, warp tile M32xN32 ->
//          ~60 regs -> 2x512 thr/SM = 32 warps/SM (2x latency cover).
//   routing: fp32 dynamic routing, one warp per pixel
//
//   x [32,32,32,8,16] f32   W [8,3,3,16,128] f32   b [1,1,8,16] f32
//   out [32,32,32,8,16] f32

#define EPS_SQ 1e-7f
#define XH_PITCH 232        // half2 units; 232 % 32 == 8 -> conflict-free LDS

__device__ __half   g_votes[32768 * 1024];          // [px][i*128+cf] fp16
__device__ uint2    g_Wfrag[8 * 9 * 16 * 32];       // fp16 B fragments

__device__ __forceinline__ void mma16(float c[4], const uint4& a, const uint2& b) {
    asm volatile(
        "mma.sync.aligned.m16n8k16.row.col.f32.f16.f16.f32 "
        "{%0,%1,%2,%3}, {%4,%5,%6,%7}, {%8,%9}, {%0,%1,%2,%3};"
        : "+f"(c[0]), "+f"(c[1]), "+f"(c[2]), "+f"(c[3])
        : "r"(a.x), "r"(a.y), "r"(a.z), "r"(a.w), "r"(b.x), "r"(b.y));
}
__device__ __forceinline__ uint32_t h2u(__half2 h) {
    return *reinterpret_cast<uint32_t*>(&h);
}

// B fragments: [r = i*9+kk][nt(16)][lane(32)] uint2.
// lane: g = lane>>2 (cf within n8), c4 = lane&3 (k pair); cf = nt*8+g.
// b.x = half2(W[fin=2c4][cf], W[2c4+1][cf]), b.y = same fin+8.
// R11: one block per r; stage the contiguous 8 KB W slice in smem first.
__global__ void prep_weights(const float* __restrict__ W) {
    __shared__ float sW[2048];                    // [fin 16][cf 128]
    const int r = blockIdx.x, t = threadIdx.x;
    const float4* Wg = reinterpret_cast<const float4*>(W) + r * 512;
    reinterpret_cast<float4*>(sW)[t]       = Wg[t];
    reinterpret_cast<float4*>(sW)[t + 256] = Wg[t + 256];
    __syncthreads();
    #pragma unroll
    for (int j = 0; j < 2; j++) {
        int fr = t + j * 256;                     // 0..511
        int lane = fr & 31, nt = fr >> 5;
        int g = lane >> 2, c4 = lane & 3;
        int cf = nt * 8 + g;
        const float* p = sW + cf;
        uint2 o;
        o.x = h2u(__floats2half2_rn(p[(2 * c4) * 128],     p[(2 * c4 + 1) * 128]));
        o.y = h2u(__floats2half2_rn(p[(2 * c4 + 8) * 128], p[(2 * c4 + 9) * 128]));
        g_Wfrag[r * 512 + fr] = o;
    }
}

// ---- K1: conv votes GEMM. grid (256 m-blocks, 8 i), 512 threads ----
// Block = 128 px (4 h-rows x 32 w of batch mblk>>3), 128 cf, one capsule i.
// 16 warps: wm = wid&3 (h-row, M32), wn = wid>>2 (N32 = 4 n8 tiles).
// K = 144 = 9 k16 steps; step kk == tap (ky,kx) = (kk/3, kk%3), 16 fins.
__global__ __launch_bounds__(512, 2)
void conv_votes_kernel(const float* __restrict__ x)
{
    __shared__ uint32_t x_h[8 * XH_PITCH];   // half2 bits: [finp 8][pix 204]
    __shared__ uint2    s_w[9 * 16 * 32];    // W frags for this i (36 KB)

    const int t = threadIdx.x, lane = t & 31, wid = t >> 5;
    const int mblk = blockIdx.x, i = blockIdx.y;
    const int b = mblk >> 3, h0 = (mblk & 7) << 2;

    // stage W fragments: 2304 uint4
    {
        const uint4* gw4 = reinterpret_cast<const uint4*>(g_Wfrag) + i * 2304;
        uint4* sw4 = reinterpret_cast<uint4*>(s_w);
        #pragma unroll
        for (int j = t; j < 2304; j += 512)
            sw4[j] = gw4[j];
    }

    // x tile (6 rows x 34 cols x 16 fin) -> packed half2, zero-pad SAME
    for (int e4 = t; e4 < 816; e4 += 512) {
        int pix = e4 >> 2, q = e4 & 3;       // q covers fin 4q..4q+3
        int r = pix / 34, c = pix - r * 34;
        int hh = h0 + r - 1, ww = c - 1;
        float4 v = make_float4(0.f, 0.f, 0.f, 0.f);
        if (hh >= 0 && hh < 32 && ww >= 0 && ww < 32)
            v = reinterpret_cast<const float4*>(x)
                  [((b * 32 + hh) * 32 + ww) * 32 + i * 4 + q];
        x_h[(q * 2 + 0) * XH_PITCH + pix] = h2u(__floats2half2_rn(v.x, v.y));
        x_h[(q * 2 + 1) * XH_PITCH + pix] = h2u(__floats2half2_rn(v.z, v.w));
    }
    __syncthreads();

    const int g = lane >> 2, c4 = lane & 3;
    const int wm = wid & 3, wn = wid >> 2;

    float acc[2][4][4];
    #pragma unroll
    for (int mt = 0; mt < 2; mt++)
        #pragma unroll
        for (int n = 0; n < 4; n++)
            #pragma unroll
            for (int j = 0; j < 4; j++) acc[mt][n][j] = 0.f;

    #pragma unroll
    for (int kk = 0; kk < 9; kk++) {
        const int ky = kk / 3, kx = kk - ky * 3;
        const int pbase = (wm + ky) * 34 + kx + g;
        uint4 a[2];
        #pragma unroll
        for (int mt = 0; mt < 2; mt++) {
            const int p0 = pbase + mt * 16;
            a[mt].x = x_h[c4 * XH_PITCH + p0];
            a[mt].y = x_h[c4 * XH_PITCH + p0 + 8];
            a[mt].z = x_h[(c4 + 4) * XH_PITCH + p0];
            a[mt].w = x_h[(c4 + 4) * XH_PITCH + p0 + 8];
        }
        #pragma unroll
        for (int n = 0; n < 4; n++) {
            uint2 bb = s_w[(kk * 16 + wn * 4 + n) * 32 + lane];
            mma16(acc[0][n], a[0], bb);
            mma16(acc[1][n], a[1], bb);
        }
    }

    // store votes fp16: u32 idx = px*512 + i*64 + (wn*4+n)*4 + c4
    uint32_t* vp = reinterpret_cast<uint32_t*>(g_votes) +
                   (size_t)(mblk * 128) * 512 + i * 64 + wn * 16 + c4;
    #pragma unroll
    for (int mt = 0; mt < 2; mt++) {
        const int m0 = wm * 32 + mt * 16 + g;
        #pragma unroll
        for (int n = 0; n < 4; n++) {
            vp[(size_t)m0 * 512 + n * 4] =
                h2u(__floats2half2_rn(acc[mt][n][0], acc[mt][n][1]));
            vp[(size_t)(m0 + 8) * 512 + n * 4] =
                h2u(__floats2half2_rn(acc[mt][n][2], acc[mt][n][3]));
        }
    }
}

// ---- K2: routing. grid 4096, 256 threads; warp w routes px = blk*8+w ----
__global__ __launch_bounds__(256)
void routing_kernel(const float* __restrict__ bias, float* __restrict__ out)
{
    const int t = threadIdx.x, lane = t & 31, wid = t >> 5;
    const int px = blockIdx.x * 8 + wid;

    const float4 bv = reinterpret_cast<const float4*>(bias)[lane];
    const uint2* vg = reinterpret_cast<const uint2*>(g_votes) + (size_t)px * 256;

    float4 v[8];
    #pragma unroll
    for (int i = 0; i < 8; i++) {
        uint2 raw = vg[i * 32 + lane];
        float2 f01 = __half22float2(*reinterpret_cast<__half2*>(&raw.x));
        float2 f23 = __half22float2(*reinterpret_cast<__half2*>(&raw.y));
        v[i] = make_float4(f01.x, f01.y, f23.x, f23.y);
    }

    float logit[8];
    #pragma unroll
    for (int i = 0; i < 8; i++) logit[i] = 0.f;
    float4 act = make_float4(0.f, 0.f, 0.f, 0.f);

    #pragma unroll
    for (int r = 0; r < 3; r++) {
        float route[8];
        if (r == 0) {
            #pragma unroll
            for (int i = 0; i < 8; i++) route[i] = 0.125f;   // softmax(0)
        } else {
            #pragma unroll
            for (int i = 0; i < 8; i++) {
                float m = logit[i];
                m = fmaxf(m, __shfl_xor_sync(0xffffffffu, m, 4));
                m = fmaxf(m, __shfl_xor_sync(0xffffffffu, m, 8));
                m = fmaxf(m, __shfl_xor_sync(0xffffffffu, m, 16));
                float e = __expf(logit[i] - m);
                float s = e;
                s += __shfl_xor_sync(0xffffffffu, s, 4);
                s += __shfl_xor_sync(0xffffffffu, s, 8);
                s += __shfl_xor_sync(0xffffffffu, s, 16);
                route[i] = e / s;
            }
        }
        float4 pre = bv;
        #pragma unroll
        for (int i = 0; i < 8; i++) {
            pre.x += route[i] * v[i].x;
            pre.y += route[i] * v[i].y;
            pre.z += route[i] * v[i].z;
            pre.w += route[i] * v[i].w;
        }
        float s2 = pre.x * pre.x + pre.y * pre.y + pre.z * pre.z + pre.w * pre.w;
        s2 += __shfl_xor_sync(0xffffffffu, s2, 1);
        s2 += __shfl_xor_sync(0xffffffffu, s2, 2);
        float scale = s2 / (1.f + s2) * rsqrtf(s2 + EPS_SQ);
        act.x = scale * pre.x;
        act.y = scale * pre.y;
        act.z = scale * pre.z;
        act.w = scale * pre.w;
        if (r < 2) {
            #pragma unroll
            for (int i = 0; i < 8; i++) {
                float d = v[i].x * act.x + v[i].y * act.y +
                          v[i].z * act.z + v[i].w * act.w;
                d += __shfl_xor_sync(0xffffffffu, d, 1);
                d += __shfl_xor_sync(0xffffffffu, d, 2);
                logit[i] += d;
            }
        }
    }

    reinterpret_cast<float4*>(out)[(size_t)px * 32 + lane] = act;
}

extern "C" void kernel_launch(void* const* d_in, const int* in_sizes, int n_in,
                              void* d_out, int out_size)
{
    const float* x    = (const float*)d_in[0];
    const float* Wt   = (const float*)d_in[1];
    const float* bias = (const float*)d_in[2];
    float* out = (float*)d_out;
    (void)in_sizes; (void)n_in; (void)out_size;

    prep_weights<<<72, 256>>>(Wt);
    dim3 gridA(256, 8);
    conv_votes_kernel<<<gridA, 512>>>(x);
    routing_kernel<<<4096, 256>>>(bias, out);
}